// round 17
// baseline (speedup 1.0000x reference)
#include <cuda_runtime.h>
#include <cuda_fp16.h>
#include <cstdint>

// ---------------------------------------------------------------------------
// cross_set_score (v13): fused kernel at 512 threads (16 warps, 1 CTA/SM).
// One CTA per unordered pair (grid 136). Per head h:
//   1. HA = xA @ W1_h  (mma; acc maps DIRECTLY to score A-operand regs)
//   2. HB = xB @ W1_h  (mma; acc packed to SMEM as score B operand)
//   3. S += W2[h] * sum leakyrelu(HA @ HB^T)   (branch-free 0.65v+0.35|v|)
// x tiles staged once (fp16, SMEM); W1 cp.async prefetch overlaps score.
// ---------------------------------------------------------------------------

#define NSET  16
#define MITEM 256
#define DIN   128
#define NHEAD 8
#define DHEAD 64
#define NPAIR 136

#define XSTR  72       // x/W1 SMEM stride in 32-bit words (64 + 8 pad)
#define BSTR  40       // H_B SMEM stride (32 + 8 pad)

// SMEM word offsets
#define OFF_XA  0
#define OFF_XB  (256 * XSTR)                 // 18432
#define OFF_W1  (2 * 256 * XSTR)             // 36864
#define OFF_BS  (OFF_W1 + 64 * XSTR)         // 41472
#define OFF_RED (OFF_BS + 256 * BSTR)        // 51712
#define SMEM_WORDS (OFF_RED + 16)
#define SMEM_BYTES (SMEM_WORDS * 4)          // ~206,912 B

#define THREADS 512

__device__ __half g_W1h[NHEAD * DHEAD * DIN];   // [head][e][d], fp16

// ---------------- helpers ----------------
__device__ __forceinline__ uint32_t packh2(float a, float b) {
    __half2 h = __floats2half2_rn(a, b);
    return *(uint32_t*)&h;
}
__device__ __forceinline__ void mma_f16(float* c, const uint32_t* a, const uint32_t* b) {
    asm volatile(
        "mma.sync.aligned.m16n8k16.row.col.f32.f16.f16.f32 "
        "{%0,%1,%2,%3}, {%4,%5,%6,%7}, {%8,%9}, {%0,%1,%2,%3};"
        : "+f"(c[0]), "+f"(c[1]), "+f"(c[2]), "+f"(c[3])
        : "r"(a[0]), "r"(a[1]), "r"(a[2]), "r"(a[3]), "r"(b[0]), "r"(b[1]));
}
__device__ __forceinline__ void cp_async16(uint32_t smem_addr, const void* gptr) {
    asm volatile("cp.async.cg.shared.global [%0], [%1], 16;"
                 :: "r"(smem_addr), "l"(gptr) : "memory");
}
__device__ __forceinline__ void cp_commit() {
    asm volatile("cp.async.commit_group;" ::: "memory");
}
__device__ __forceinline__ void cp_wait0() {
    asm volatile("cp.async.wait_group 0;" ::: "memory");
}
__device__ __forceinline__ uint32_t smem_u32(const void* p) {
    return (uint32_t)__cvta_generic_to_shared(p);
}

// ============================================================================
// Kernel 0: transpose + fp16-round W1 -> g_W1h[head][e][d].
// ============================================================================
__global__ void prep_w1(const float* __restrict__ W1)
{
    const int idx = blockIdx.x * 1024 + threadIdx.x;   // 65536 total
    const int he  = idx >> 7;            // head*64 + e
    const int d   = idx & 127;
    g_W1h[idx] = __float2half(W1[d * (NHEAD * DHEAD) + he]);
}

// ============================================================================
// Fused kernel: grid = 136 pairs, 512 threads (16 warps), 1 CTA/SM.
// Warp owns 16 rows of the pair tile through proj AND score.
// ============================================================================
__global__ __launch_bounds__(THREADS, 1)
void fused_kernel(const float* __restrict__ x,
                  const float* __restrict__ nItem,
                  const float* __restrict__ W2,
                  float* __restrict__ out)
{
    extern __shared__ uint32_t sm[];
    uint32_t* xA = sm + OFF_XA;          // [256][XSTR] fp16x2 words
    uint32_t* xB = sm + OFF_XB;          // [256][XSTR]
    uint32_t* w1 = sm + OFF_W1;          // [64][XSTR]
    uint32_t* Bs = sm + OFF_BS;          // [256][BSTR]
    float*   red = (float*)(sm + OFF_RED);

    const int tid  = threadIdx.x;
    const int wid  = tid >> 5;           // 0..15
    const int lane = tid & 31;
    const int r    = lane >> 2;
    const int c    = lane & 3;
    const int rowbase = wid * 16;        // warp's 16 rows

    // pair -> (ii <= jj)
    int q = blockIdx.x, jj = 0;
    while (q >= jj + 1) { q -= (jj + 1); ++jj; }
    const int ii = q;

    const uint32_t w1_base = smem_u32(w1);
    auto stage_w1 = [&](int h) {
        const char* src = (const char*)(g_W1h + (size_t)h * DHEAD * DIN);
        #pragma unroll
        for (int it = 0; it < 2; ++it) {
            int idx = tid + it * THREADS;
            int e = idx >> 4, dq = idx & 15;           // 16 uint4 per row
            cp_async16(w1_base + (e * XSTR + dq * 4) * 4, src + idx * 16);
        }
        cp_commit();
    };

    // ---- prologue: stage W1[0]; stage xA, xB (fp32 -> fp16) ----
    stage_w1(0);
    {
        const float4* gA = (const float4*)(x + (size_t)(jj * NSET + ii) * MITEM * DIN);
        const float4* gB = (const float4*)(x + (size_t)(ii * NSET + jj) * MITEM * DIN);
        #pragma unroll 4
        for (int it = 0; it < 16; ++it) {
            int idx = tid + it * THREADS;
            int row = idx >> 5, fq = idx & 31;
            float4 va = gA[idx];
            float4 vb = gB[idx];
            uint2 wa = { packh2(va.x, va.y), packh2(va.z, va.w) };
            uint2 wb = { packh2(vb.x, vb.y), packh2(vb.z, vb.w) };
            *(uint2*)&xA[row * XSTR + 2 * fq] = wa;
            *(uint2*)&xB[row * XSTR + 2 * fq] = wb;
        }
    }
    cp_wait0();
    __syncthreads();

    float stot = 0.f;

    #pragma unroll 1
    for (int h = 0; h < NHEAD; ++h) {
        uint32_t aF[4][4];               // score A operand (held in regs)

        // ================= projection of A then B =================
        #pragma unroll 1
        for (int pass = 0; pass < 2; ++pass) {
            const uint32_t* xs = pass ? xB : xA;
            float acc[8][4];             // [n8-tile][4]
            #pragma unroll
            for (int nt = 0; nt < 8; ++nt)
                #pragma unroll
                for (int e = 0; e < 4; ++e) acc[nt][e] = 0.f;

            #pragma unroll
            for (int ks = 0; ks < 8; ++ks) {
                uint32_t aX[4];
                {
                    uint2 lo = *(const uint2*)&xs[(rowbase + r) * XSTR + ks * 8 + 2 * c];
                    uint2 hi = *(const uint2*)&xs[(rowbase + r + 8) * XSTR + ks * 8 + 2 * c];
                    aX[0] = lo.x; aX[2] = lo.y;
                    aX[1] = hi.x; aX[3] = hi.y;
                }
                #pragma unroll
                for (int nt = 0; nt < 8; ++nt) {
                    uint2 b = *(const uint2*)&w1[(nt * 8 + r) * XSTR + ks * 8 + 2 * c];
                    mma_f16(acc[nt], aX, (const uint32_t*)&b);
                }
            }

            if (pass == 0) {
                // acc -> score A regs (direct layout correspondence)
                #pragma unroll
                for (int k = 0; k < 4; ++k) {
                    aF[k][0] = packh2(acc[2 * k][0],     acc[2 * k][1]);
                    aF[k][1] = packh2(acc[2 * k][2],     acc[2 * k][3]);
                    aF[k][2] = packh2(acc[2 * k + 1][0], acc[2 * k + 1][1]);
                    aF[k][3] = packh2(acc[2 * k + 1][2], acc[2 * k + 1][3]);
                }
            } else {
                // acc -> Bs SMEM (score B operand), conflict-free STS.64
                #pragma unroll
                for (int k = 0; k < 4; ++k) {
                    uint2 lo = { packh2(acc[2 * k][0],     acc[2 * k][1]),
                                 packh2(acc[2 * k + 1][0], acc[2 * k + 1][1]) };
                    uint2 hi = { packh2(acc[2 * k][2],     acc[2 * k][3]),
                                 packh2(acc[2 * k + 1][2], acc[2 * k + 1][3]) };
                    *(uint2*)&Bs[(rowbase + r) * BSTR + k * 8 + 2 * c]     = lo;
                    *(uint2*)&Bs[(rowbase + r + 8) * BSTR + k * 8 + 2 * c] = hi;
                }
            }
        }

        __syncthreads();                 // Bs published; W1[h] reads done
        if (h < NHEAD - 1) stage_w1(h + 1);   // prefetch overlaps score

        // ================= score: 32 n-tiles, ILP-2 via nt pairs ==========
        float s1 = 0.f, s2 = 0.f;
        #pragma unroll 1
        for (int nt = 0; nt < 32; nt += 2) {
            float acc0[4] = {0.f, 0.f, 0.f, 0.f};
            float acc1[4] = {0.f, 0.f, 0.f, 0.f};
            #pragma unroll
            for (int k = 0; k < 4; ++k) {
                uint2 b0 = *(const uint2*)&Bs[(nt * 8 + r) * BSTR + k * 8 + 2 * c];
                uint2 b1 = *(const uint2*)&Bs[((nt + 1) * 8 + r) * BSTR + k * 8 + 2 * c];
                mma_f16(acc0, aF[k], (const uint32_t*)&b0);
                mma_f16(acc1, aF[k], (const uint32_t*)&b1);
            }
            #pragma unroll
            for (int e = 0; e < 4; ++e) {
                s1 += acc0[e];  s2 += fabsf(acc0[e]);
                s1 += acc1[e];  s2 += fabsf(acc1[e]);
            }
        }
        stot += W2[h] * (0.65f * s1 + 0.35f * s2);

        if (h < NHEAD - 1) cp_wait0();   // W1[h+1] landed
        __syncthreads();                 // Bs reads done; W1[h+1] visible
    }

    // ---- CTA reduce + write both symmetric outputs ----
    #pragma unroll
    for (int off = 16; off; off >>= 1)
        stot += __shfl_xor_sync(0xffffffffu, stot, off);
    if (lane == 0) red[wid] = stot;
    __syncthreads();
    if (tid == 0) {
        float s = 0.f;
        #pragma unroll
        for (int w = 0; w < 16; ++w) s += red[w];
        float v = s / (8.0f * nItem[ii] * nItem[jj]);   // 8 = sqrt(D=64)
        out[jj * NSET + ii] = v;
        out[ii * NSET + jj] = v;
    }
}

// ---------------- entry point ----------------
extern "C" void kernel_launch(void* const* d_in, const int* in_sizes, int n_in,
                              void* d_out, int out_size)
{
    const float* x = nullptr;
    const float* nItem = nullptr;
    const float* W1 = nullptr;
    const float* W2 = nullptr;
    for (int k = 0; k < n_in; ++k) {
        switch (in_sizes[k]) {
            case NSET * NSET * MITEM * DIN: x     = (const float*)d_in[k]; break;
            case NSET:                      nItem = (const float*)d_in[k]; break;
            case DIN * NHEAD * DHEAD:       W1    = (const float*)d_in[k]; break;
            case NHEAD:                     W2    = (const float*)d_in[k]; break;
        }
    }

    static bool attr_done = false;
    if (!attr_done) {
        cudaFuncSetAttribute(fused_kernel,
                             cudaFuncAttributeMaxDynamicSharedMemorySize, SMEM_BYTES);
        attr_done = true;
    }

    prep_w1<<<64, 1024>>>(W1);
    fused_kernel<<<NPAIR, THREADS, SMEM_BYTES>>>(x, nItem, W2, (float*)d_out);
}